// round 12
// baseline (speedup 1.0000x reference)
#include <cuda_runtime.h>
#include <cuda_bf16.h>
#include <cstdint>

#define BDIM 512
#define FDIM 1024
#define H1D  512
#define H2D  256
#define OUTD 128
#define KDD  5
#define NMD  (OUTD*KDD)   // 640
#define ZD   384
#define LOG2E 1.44269504f

// Prepped weights: bf16 hi/lo, transposed to [n][k]
#define WOFF_W1 0
#define WOFF_W2 524288
#define WOFF_T  655360
#define WOFF_W3 819200
#define WTOT    868352
__device__ __nv_bfloat16 g_Wbh[WTOT];
__device__ __nv_bfloat16 g_Wbl[WTOT];

// Activations / split-K partials
__device__ float g_p1[8 * BDIM * H1D];
__device__ float g_h1[BDIM * H1D];
__device__ float g_p2[8 * BDIM * H2D];
__device__ float g_z [BDIM * ZD];      // cols 0..255 = h2, 256..383 = o_b
__device__ float g_p3[4 * BDIM * NMD];
__device__ float g_M [BDIM * NMD];     // prescaled by log2e
__device__ float g_p4[6 * BDIM * OUTD];
__device__ float g_z3[BDIM * OUTD];

// Per-tile completion counters (atomicInc wrap -> self-reset across replays)
__device__ unsigned g_cnt1[32];
__device__ unsigned g_cnt2[16];
__device__ unsigned g_cnt3[40];
__device__ unsigned g_cnt4[8];

__device__ __forceinline__ float lrelu(float v) { return fmaxf(v, 0.2f * v); }

__device__ __forceinline__ uint32_t smem_u32(const void* p) {
    uint32_t a;
    asm("{ .reg .u64 t; cvta.to.shared.u64 t, %1; cvt.u32.u64 %0, t; }"
        : "=r"(a) : "l"(p));
    return a;
}
__device__ __forceinline__ void ldmx4(uint32_t* r, uint32_t addr) {
    asm volatile("ldmatrix.sync.aligned.m8n8.x4.shared.b16 {%0,%1,%2,%3}, [%4];"
                 : "=r"(r[0]), "=r"(r[1]), "=r"(r[2]), "=r"(r[3]) : "r"(addr));
}
__device__ __forceinline__ void mma16816(float* d, const uint32_t* a,
                                         uint32_t b0, uint32_t b1) {
    asm volatile("mma.sync.aligned.m16n8k16.row.col.f32.bf16.bf16.f32 "
                 "{%0,%1,%2,%3}, {%4,%5,%6,%7}, {%8,%9}, {%0,%1,%2,%3};"
                 : "+f"(d[0]), "+f"(d[1]), "+f"(d[2]), "+f"(d[3])
                 : "r"(a[0]), "r"(a[1]), "r"(a[2]), "r"(a[3]), "r"(b0), "r"(b1));
}
__device__ __forceinline__ uint32_t bf16pack(float lo_elem, float hi_elem) {
    uint32_t r;
    asm("cvt.rn.bf16x2.f32 %0, %1, %2;" : "=r"(r) : "f"(hi_elem), "f"(lo_elem));
    return r;
}

// ---------------------------------------------------------------------------
// Prep: W [K][N] fp32 -> Wbh/Wbl [n][k] bf16 (transpose + hi/lo split)
// ---------------------------------------------------------------------------
__global__ __launch_bounds__(256)
void prep_k(const float* __restrict__ W1, const float* __restrict__ W2,
            const float* __restrict__ T,  const float* __restrict__ W3)
{
    __shared__ float s[32][33];
    int b = blockIdx.x;
    const float* src; int K, N; size_t off; int rel;
    if      (b < 512) { src = W1; K = 1024; N = 512; off = WOFF_W1; rel = b; }
    else if (b < 640) { src = W2; K = 512;  N = 256; off = WOFF_W2; rel = b - 512; }
    else if (b < 800) { src = T;  K = 256;  N = 640; off = WOFF_T;  rel = b - 640; }
    else              { src = W3; K = 384;  N = 128; off = WOFF_W3; rel = b - 800; }
    int ktiles = K / 32;
    int k0 = (rel % ktiles) * 32, n0 = (rel / ktiles) * 32;
    int tx = threadIdx.x & 31, ty = threadIdx.x >> 5;

    #pragma unroll
    for (int i = 0; i < 4; i++)
        s[ty + i * 8][tx] = src[(size_t)(k0 + ty + i * 8) * N + n0 + tx];
    __syncthreads();
    #pragma unroll
    for (int i = 0; i < 4; i++) {
        int n = n0 + ty + i * 8, k = k0 + tx;
        float v = s[tx][ty + i * 8];
        __nv_bfloat16 h = __float2bfloat16_rn(v);
        float l = v - __bfloat162float(h);
        g_Wbh[off + (size_t)n * K + k] = h;
        g_Wbl[off + (size_t)n * K + k] = __float2bfloat16_rn(l);
    }
}

// ---------------------------------------------------------------------------
// Tensor-core GEMM (mma.sync bf16 3-pass) with FUSED split-K reduction:
// each CTA computes a 128x64 x Kc partial; the last-arriving CTA per output
// tile sums all SPLIT partials (L2-hot) and applies the epilogue.
// MODE 0: lrelu(v + bias[n]); MODE 1: v * LOG2E.
// ---------------------------------------------------------------------------
#define SA_ST 80
#define SAH 0
#define SAL 10240
#define SBH 20480
#define SBL 25600
#define SM_TOT 30720

template<int SPLIT, int MODE>
__global__ __launch_bounds__(256)
void tgemm(const float* __restrict__ A, int lda,
           const __nv_bfloat16* __restrict__ Bhg,
           const __nv_bfloat16* __restrict__ Blg, int Kb,
           float* __restrict__ Cpart, size_t cpStride, int ldc, int Kc,
           const float* __restrict__ bias,
           float* __restrict__ Out, int ld_out,
           unsigned* __restrict__ cnt)
{
    __shared__ __align__(16) char sb[SM_TOT];
    __shared__ int sflag;
    const int tid = threadIdx.x, lane = tid & 31, wid = tid >> 5;
    const int wm = wid >> 1, wn = wid & 1;
    const int n0 = blockIdx.x * 64, row0 = blockIdx.y * 128;
    const int kbase = blockIdx.z * Kc;
    const uint32_t sbase = smem_u32(sb);

    float acc[2][4][4] = {};

    const int ar = tid >> 1, ah = tid & 1;
    const int br = tid >> 2, bq = tid & 3;
    float4 pa[4]; uint4 pbh, pbl;

    auto fetch = [&](int k0) {
        const float* ap = A + (size_t)(row0 + ar) * lda + k0 + ah * 16;
        pa[0] = *(const float4*)(ap);
        pa[1] = *(const float4*)(ap + 4);
        pa[2] = *(const float4*)(ap + 8);
        pa[3] = *(const float4*)(ap + 12);
        pbh = *(const uint4*)(Bhg + (size_t)(n0 + br) * Kb + k0 + bq * 8);
        pbl = *(const uint4*)(Blg + (size_t)(n0 + br) * Kb + k0 + bq * 8);
    };
    auto stick = [&]() {
        float e[16] = {pa[0].x, pa[0].y, pa[0].z, pa[0].w,
                       pa[1].x, pa[1].y, pa[1].z, pa[1].w,
                       pa[2].x, pa[2].y, pa[2].z, pa[2].w,
                       pa[3].x, pa[3].y, pa[3].z, pa[3].w};
        uint32_t hp[8], lp[8];
        #pragma unroll
        for (int j = 0; j < 8; j++) {
            float a0 = e[2 * j], a1 = e[2 * j + 1];
            __nv_bfloat16 h0 = __float2bfloat16_rn(a0);
            __nv_bfloat16 h1 = __float2bfloat16_rn(a1);
            hp[j] = bf16pack(a0, a1);
            lp[j] = bf16pack(a0 - __bfloat162float(h0), a1 - __bfloat162float(h1));
        }
        char* da = sb + SAH + ar * SA_ST + ah * 32;
        *(uint4*)(da)      = make_uint4(hp[0], hp[1], hp[2], hp[3]);
        *(uint4*)(da + 16) = make_uint4(hp[4], hp[5], hp[6], hp[7]);
        char* dl = sb + SAL + ar * SA_ST + ah * 32;
        *(uint4*)(dl)      = make_uint4(lp[0], lp[1], lp[2], lp[3]);
        *(uint4*)(dl + 16) = make_uint4(lp[4], lp[5], lp[6], lp[7]);
        *(uint4*)(sb + SBH + br * SA_ST + bq * 16) = pbh;
        *(uint4*)(sb + SBL + br * SA_ST + bq * 16) = pbl;
    };

    fetch(kbase);
    stick();
    __syncthreads();

    const int nch = Kc / 32;
    for (int ch = 0; ch < nch; ch++) {
        const bool nxt = (ch + 1) < nch;
        if (nxt) fetch(kbase + (ch + 1) * 32);

        #pragma unroll
        for (int kt = 0; kt < 2; kt++) {
            uint32_t afh[2][4], afl[2][4], bfh[2][4], bfl[2][4];
            #pragma unroll
            for (int mt = 0; mt < 2; mt++) {
                uint32_t ad = sbase + SAH + (wm * 32 + mt * 16 + (lane & 15)) * SA_ST
                            + kt * 32 + ((lane >> 4) << 4);
                ldmx4(afh[mt], ad);
                ldmx4(afl[mt], ad + (SAL - SAH));
            }
            #pragma unroll
            for (int bt = 0; bt < 2; bt++) {
                uint32_t bd = sbase + SBH + (wn * 32 + bt * 16 + (lane & 15)) * SA_ST
                            + kt * 32 + ((lane >> 4) << 4);
                ldmx4(bfh[bt], bd);
                ldmx4(bfl[bt], bd + (SBL - SBH));
            }
            #pragma unroll
            for (int mt = 0; mt < 2; mt++)
                #pragma unroll
                for (int j = 0; j < 4; j++) {
                    int t = j >> 1, o = j & 1;
                    uint32_t b0h = bfh[t][o], b1h = bfh[t][o + 2];
                    uint32_t b0l = bfl[t][o], b1l = bfl[t][o + 2];
                    mma16816(acc[mt][j], afh[mt], b0h, b1h);
                    mma16816(acc[mt][j], afl[mt], b0h, b1h);
                    mma16816(acc[mt][j], afh[mt], b0l, b1l);
                }
        }
        __syncthreads();
        if (nxt) { stick(); __syncthreads(); }
    }

    // Store this split's partial
    float* cp = Cpart + (size_t)blockIdx.z * cpStride;
    #pragma unroll
    for (int mt = 0; mt < 2; mt++)
        #pragma unroll
        for (int j = 0; j < 4; j++) {
            int r = row0 + wm * 32 + mt * 16 + (lane >> 2);
            int c = n0 + wn * 32 + j * 8 + (lane & 3) * 2;
            *(float2*)&cp[(size_t)r * ldc + c] =
                make_float2(acc[mt][j][0], acc[mt][j][1]);
            *(float2*)&cp[(size_t)(r + 8) * ldc + c] =
                make_float2(acc[mt][j][2], acc[mt][j][3]);
        }

    // Last-arrival fused reduction + epilogue (round-9-proven pattern)
    __threadfence();
    __syncthreads();
    if (tid == 0)
        sflag = (atomicInc(&cnt[blockIdx.y * gridDim.x + blockIdx.x],
                           SPLIT - 1) == SPLIT - 1);
    __syncthreads();
    if (!sflag) return;

    #pragma unroll
    for (int it = 0; it < 8; it++) {
        int idx = tid + it * 256;
        int r = idx >> 4, c4 = (idx & 15) * 4;     // 16 float4 per 64-col row
        const float* p = Cpart + (size_t)(row0 + r) * ldc + n0 + c4;
        float4 v = *(const float4*)p;
        #pragma unroll
        for (int s = 1; s < SPLIT; s++) {
            float4 u = *(const float4*)(p + (size_t)s * cpStride);
            v.x += u.x; v.y += u.y; v.z += u.z; v.w += u.w;
        }
        if (MODE == 0) {
            float4 bv = *(const float4*)(bias + n0 + c4);
            v.x = lrelu(v.x + bv.x);
            v.y = lrelu(v.y + bv.y);
            v.z = lrelu(v.z + bv.z);
            v.w = lrelu(v.w + bv.w);
        } else {
            v.x *= LOG2E; v.y *= LOG2E; v.z *= LOG2E; v.w *= LOG2E;
        }
        *(float4*)(Out + (size_t)(row0 + r) * ld_out + n0 + c4) = v;
    }
}

// ---------------------------------------------------------------------------
// Pairwise: o_b[j,o] = sum_i exp2(-|M[i,o,:]-M[j,o,:]|_1) - 1   (M prescaled)
// Packed f32x2 diffs (exact: fma with multiplier 1), abs folded into FADD.
// grid (o=128, jh=2), 256 threads. Writes z[:, 256+o].
// ---------------------------------------------------------------------------
__global__ __launch_bounds__(256)
void pairwise_k(const float* __restrict__ M, float* __restrict__ z)
{
    __shared__ float4 s4[BDIM];
    __shared__ float  s1[BDIM];
    const int o = blockIdx.x, jh = blockIdx.y;
    const int tid = threadIdx.x;

    #pragma unroll
    for (int it = 0; it < 10; it++) {
        int idx = tid + it * 256;
        int i = idx / 5, k = idx - i * 5;
        float v = M[(size_t)i * NMD + o * KDD + k];
        if (k < 4) ((float*)s4)[i * 4 + k] = v;
        else       s1[i] = v;
    }
    __syncthreads();

    const int j = jh * 256 + tid;
    float4 m4 = s4[j];
    float  m4e = s1[j];
    unsigned long long one2, mn01, mn23;
    asm("mov.b64 %0, {%1,%1};" : "=l"(one2) : "f"(1.0f));
    asm("mov.b64 %0, {%1,%2};" : "=l"(mn01) : "f"(-m4.x), "f"(-m4.y));
    asm("mov.b64 %0, {%1,%2};" : "=l"(mn23) : "f"(-m4.z), "f"(-m4.w));

    float acc0 = 0.f, acc1 = 0.f;
    #pragma unroll 8
    for (int i = 0; i < BDIM; i++) {
        ulonglong2 v = *(const ulonglong2*)&s4[i];
        float w = s1[i];
        unsigned long long d01, d23;
        asm("fma.rn.f32x2 %0, %1, %2, %3;" : "=l"(d01) : "l"(v.x), "l"(one2), "l"(mn01));
        asm("fma.rn.f32x2 %0, %1, %2, %3;" : "=l"(d23) : "l"(v.y), "l"(one2), "l"(mn23));
        float d0, d1, d2, d3;
        asm("mov.b64 {%0,%1}, %2;" : "=f"(d0), "=f"(d1) : "l"(d01));
        asm("mov.b64 {%0,%1}, %2;" : "=f"(d2), "=f"(d3) : "l"(d23));
        float n = (fabsf(d0) + fabsf(d1)) + (fabsf(d2) + fabsf(d3)) + fabsf(w - m4e);
        float e;
        asm("ex2.approx.f32 %0, %1;" : "=f"(e) : "f"(-n));
        if (i & 1) acc1 += e; else acc0 += e;
    }
    z[(size_t)j * ZD + H2D + o] = acc0 + acc1 - 1.0f;
}

// ---------------------------------------------------------------------------
__global__ __launch_bounds__(256)
void final_k(const float* __restrict__ z3, const float* __restrict__ W4,
             const float* __restrict__ b4, float* __restrict__ out)
{
    int gw = blockIdx.x * 8 + (threadIdx.x >> 5);
    int lane = threadIdx.x & 31;
    float sum = 0.f;
    #pragma unroll
    for (int it = 0; it < 4; it++)
        sum += z3[(size_t)gw * OUTD + it * 32 + lane] * W4[it * 32 + lane];
    #pragma unroll
    for (int off = 16; off; off >>= 1)
        sum += __shfl_xor_sync(0xffffffffu, sum, off);
    if (lane == 0) out[gw] = sum + b4[0];
}

// ---------------------------------------------------------------------------
extern "C" void kernel_launch(void* const* d_in, const int* in_sizes, int n_in,
                              void* d_out, int out_size)
{
    (void)in_sizes; (void)n_in; (void)out_size;
    const float* x  = (const float*)d_in[0];
    const float* W1 = (const float*)d_in[1];
    const float* b1 = (const float*)d_in[2];
    const float* W2 = (const float*)d_in[3];
    const float* b2 = (const float*)d_in[4];
    const float* T  = (const float*)d_in[5];
    const float* W3 = (const float*)d_in[6];
    const float* b3 = (const float*)d_in[7];
    const float* W4 = (const float*)d_in[8];
    const float* b4 = (const float*)d_in[9];
    float* out = (float*)d_out;

    float *p1, *h1, *p2, *z, *p3, *M, *p4, *z3;
    __nv_bfloat16 *Wbh, *Wbl;
    unsigned *c1, *c2, *c3, *c4;
    cudaGetSymbolAddress((void**)&p1, g_p1);
    cudaGetSymbolAddress((void**)&h1, g_h1);
    cudaGetSymbolAddress((void**)&p2, g_p2);
    cudaGetSymbolAddress((void**)&z,  g_z);
    cudaGetSymbolAddress((void**)&p3, g_p3);
    cudaGetSymbolAddress((void**)&M,  g_M);
    cudaGetSymbolAddress((void**)&p4, g_p4);
    cudaGetSymbolAddress((void**)&z3, g_z3);
    cudaGetSymbolAddress((void**)&Wbh, g_Wbh);
    cudaGetSymbolAddress((void**)&Wbl, g_Wbl);
    cudaGetSymbolAddress((void**)&c1, g_cnt1);
    cudaGetSymbolAddress((void**)&c2, g_cnt2);
    cudaGetSymbolAddress((void**)&c3, g_cnt3);
    cudaGetSymbolAddress((void**)&c4, g_cnt4);

    // Weights -> bf16 hi/lo, transposed [n][k]
    prep_k<<<848, 256>>>(W1, W2, T, W3);

    // GEMM1: x @ W1 (split-K=8, Kc=128) -> h1 = lrelu(.+b1). 256 CTAs.
    tgemm<8,0><<<dim3(8,4,8), 256>>>(x, FDIM, Wbh + WOFF_W1, Wbl + WOFF_W1, FDIM,
                                     p1, (size_t)BDIM * H1D, H1D, 128,
                                     b1, h1, H1D, c1);
    // GEMM2: h1 @ W2 (split-K=8, Kc=64) -> z[:, :256] = lrelu(.+b2). 128 CTAs.
    tgemm<8,0><<<dim3(4,4,8), 256>>>(h1, H1D, Wbh + WOFF_W2, Wbl + WOFF_W2, H1D,
                                     p2, (size_t)BDIM * H2D, H2D, 64,
                                     b2, z, ZD, c2);
    // GEMM3: h2 @ T (split-K=4, Kc=64) -> M = . * log2e. 160 CTAs.
    tgemm<4,1><<<dim3(10,4,4), 256>>>(z, ZD, Wbh + WOFF_T, Wbl + WOFF_T, H2D,
                                      p3, (size_t)BDIM * NMD, NMD, 64,
                                      nullptr, M, NMD, c3);
    // Pairwise -> z[:, 256:]
    pairwise_k<<<dim3(OUTD, 2), 256>>>(M, z);
    // GEMM4: z @ W3 (split-K=6, Kc=64) -> z3 = lrelu(.+b3). 48 CTAs.
    tgemm<6,0><<<dim3(2,4,6), 256>>>(z, ZD, Wbh + WOFF_W3, Wbl + WOFF_W3, ZD,
                                     p4, (size_t)BDIM * OUTD, OUTD, 64,
                                     b3, z3, OUTD, c4);
    // out = z3 @ W4 + b4
    final_k<<<64, 256>>>(z3, W4, b4, out);
}